// round 11
// baseline (speedup 1.0000x reference)
#include <cuda_runtime.h>
#include <cuda_fp16.h>

#define N_NODES 100000
#define N_EDGES 1000000
#define IN_DIM  37
#define HID     64
#define BN_EPS  1e-5f

#define SCAN_B   1024
#define N_SBLK   ((N_NODES + SCAN_B - 1) / SCAN_B)   // 98

// packed fp32x2 FMA (sm_100+): d = a*b + c, all .b64 packed (lo,hi) floats
#define FMA_F32X2(d, a, b, c) \
    asm("fma.rn.f32x2 %0, %1, %2, %3;" : "=l"(d) : "l"(a), "l"(b), "l"(c))
#define PACK2(out, u) \
    asm("mov.b64 %0, {%1, %1};" : "=l"(out) : "r"(u))
#define UNPACK2(lo, hi, in) \
    asm("mov.b64 {%0, %1}, %2;" : "=r"(lo), "=r"(hi) : "l"(in))

// -------- scratch (device globals; no allocation allowed) --------
__device__ __half g_hsh[N_NODES * HID];  // dinv-scaled GEMM output, fp16 (gather buffer)
__device__ float  g_x0 [N_NODES * HID];  // layer-1 output
__device__ float  g_x1 [N_NODES * HID];  // layer-2 output
__device__ int    g_deg   [N_NODES];     // real in-degree (no self loop)
__device__ float  g_dinv  [N_NODES];
__device__ int    g_part  [N_NODES];
__device__ int    g_bsum  [N_SBLK];
__device__ int    g_boff  [N_SBLK];
__device__ int    g_start [N_NODES];     // CSR row offsets (by col/target)
__device__ int    g_cursor[N_NODES];
__device__ int    g_csr   [N_EDGES];     // source node per CSR slot
__device__ float  g_s3[3 * HID];         // folded BN scale
__device__ float  g_t3[3 * HID];         // folded BN shift
__device__ int    g_is64;

__device__ __forceinline__ int edge_at(const void* ei, long long idx, int is64) {
    if (is64) return (int)((const long long*)ei)[idx];
    return ((const int*)ei)[idx];
}

// -------- init: dtype detection + degree zero (merged) --------
__global__ void init_all(const unsigned* __restrict__ ei_raw) {
    int v = blockIdx.x * blockDim.x + threadIdx.x;
    if (v < N_NODES) g_deg[v] = 0;
    if (blockIdx.x == 0 && threadIdx.x == 0) {
        int ok = 1;
        #pragma unroll 1
        for (int i = 0; i < 64; i++)
            if (ei_raw[2 * i + 1] != 0u) ok = 0;
        g_is64 = ok;  // all high words zero -> int64 layout
    }
}

__global__ void deg_count(const void* __restrict__ ei) {
    int e = blockIdx.x * blockDim.x + threadIdx.x;
    if (e < N_EDGES) {
        int is64 = g_is64;
        int col = edge_at(ei, (long long)N_EDGES + e, is64);
        atomicAdd(&g_deg[col], 1);
    }
}

// -------- exclusive scan of g_deg --------
__global__ void scan1() {
    __shared__ int s[SCAN_B];
    int t = threadIdx.x;
    int g = blockIdx.x * SCAN_B + t;
    int v = (g < N_NODES) ? g_deg[g] : 0;
    s[t] = v;
    __syncthreads();
    #pragma unroll
    for (int off = 1; off < SCAN_B; off <<= 1) {
        int x = (t >= off) ? s[t - off] : 0;
        __syncthreads();
        s[t] += x;
        __syncthreads();
    }
    int incl = s[t];
    if (g < N_NODES) g_part[g] = incl - v;
    if (t == SCAN_B - 1) g_bsum[blockIdx.x] = incl;
}

// scan of block sums (threads 0..127) + BN fold (threads 0..191), merged
__global__ void scan2_bn(const float* __restrict__ b,
                         const float* __restrict__ gamma,
                         const float* __restrict__ beta,
                         const float* __restrict__ mean,
                         const float* __restrict__ var) {
    __shared__ int s[256];
    int t = threadIdx.x;
    int v = (t < N_SBLK) ? g_bsum[t] : 0;
    s[t] = v;
    __syncthreads();
    #pragma unroll
    for (int off = 1; off < 128; off <<= 1) {
        int x = (t >= off && t < 128) ? s[t - off] : 0;
        __syncthreads();
        if (t < 128) s[t] += x;
        __syncthreads();
    }
    if (t < N_SBLK) g_boff[t] = s[t] - v;

    if (t < 3 * HID) {
        float sc = gamma[t] * rsqrtf(var[t] + BN_EPS);
        g_s3[t] = sc;
        g_t3[t] = (b[t] - mean[t]) * sc + beta[t];
    }
}

__global__ void scan3() {
    int v = blockIdx.x * blockDim.x + threadIdx.x;
    if (v < N_NODES) {
        int st = g_part[v] + g_boff[v >> 10];
        g_start[v]  = st;
        g_cursor[v] = st;
        g_dinv[v]   = rsqrtf((float)(g_deg[v] + 1));
    }
}

__global__ void csr_fill(const void* __restrict__ ei) {
    int e = blockIdx.x * blockDim.x + threadIdx.x;
    if (e < N_EDGES) {
        int is64 = g_is64;
        int row = edge_at(ei, e, is64);
        int col = edge_at(ei, (long long)N_EDGES + e, is64);
        int pos = atomicAdd(&g_cursor[col], 1);
        g_csr[pos] = row;
    }
}

// -------- GEMM (f32x2 packed FMA): hsh[v,:] = fp16( dinv[v] * (x[v,:] @ W) )
// sel: 0 -> xext (harness input), 1 -> g_x0, 2 -> g_x1
template <int K>
__global__ void gemm_scale(const float* __restrict__ xext, int sel,
                           const float* __restrict__ W) {
    __shared__ __align__(16) float Wsh[K * HID];
    for (int i = threadIdx.x; i < K * HID; i += blockDim.x) Wsh[i] = W[i];
    __syncthreads();

    int v = blockIdx.x * blockDim.x + threadIdx.x;
    if (v >= N_NODES) return;

    const float* x = (sel == 0) ? xext : (sel == 1 ? g_x0 : g_x1);

    unsigned long long acc[32];   // 32 packed f32x2 = 64 fp32 accumulators
    #pragma unroll
    for (int j = 0; j < 32; j++) acc[j] = 0ULL;

    const float* xr = x + v * K;
    #pragma unroll 2
    for (int k = 0; k < K; k++) {
        unsigned xu = __float_as_uint(xr[k]);
        unsigned long long xp;
        PACK2(xp, xu);                      // (xv, xv)
        const ulonglong2* wr = (const ulonglong2*)(Wsh + k * HID);
        #pragma unroll
        for (int j = 0; j < 16; j++) {      // 16 LDS.128 -> 32 packed pairs
            ulonglong2 w = wr[j];
            FMA_F32X2(acc[2 * j],     xp, w.x, acc[2 * j]);
            FMA_F32X2(acc[2 * j + 1], xp, w.y, acc[2 * j + 1]);
        }
    }

    float d = g_dinv[v];
    uint4* out = (uint4*)(g_hsh + (v << 6));
    #pragma unroll
    for (int j = 0; j < 8; j++) {           // 8 cols per uint4 store
        unsigned u[8];
        float f[8];
        UNPACK2(u[0], u[1], acc[4 * j]);
        UNPACK2(u[2], u[3], acc[4 * j + 1]);
        UNPACK2(u[4], u[5], acc[4 * j + 2]);
        UNPACK2(u[6], u[7], acc[4 * j + 3]);
        #pragma unroll
        for (int m = 0; m < 8; m++) f[m] = __uint_as_float(u[m]) * d;
        __half2 h0 = __floats2half2_rn(f[0], f[1]);
        __half2 h1 = __floats2half2_rn(f[2], f[3]);
        __half2 h2 = __floats2half2_rn(f[4], f[5]);
        __half2 h3 = __floats2half2_rn(f[6], f[7]);
        uint4 pk;
        pk.x = *(unsigned*)&h0;
        pk.y = *(unsigned*)&h1;
        pk.z = *(unsigned*)&h2;
        pk.w = *(unsigned*)&h3;
        out[j] = pk;
    }
}

// -------- fused aggregate + epilogue: warp-per-node, 4 sub-lists, unroll 4 --
__device__ __forceinline__ void acc8(float* a, uint4 v) {
    const __half2* h = (const __half2*)&v;
    #pragma unroll
    for (int k = 0; k < 4; k++) {
        float2 f = __half22float2(h[k]);
        a[2 * k]     += f.x;
        a[2 * k + 1] += f.y;
    }
}

__global__ void aggregate_ep(int osel, int rsel, int lsel,
                             float* __restrict__ dout) {
    int lane = threadIdx.x & 31;
    int warp = threadIdx.x >> 5;
    int v = blockIdx.x * 8 + warp;         // 256 threads = 8 warps = 8 nodes
    if (v >= N_NODES) return;

    int c   = lane & 7;
    int sub = lane >> 3;

    int start = g_start[v];
    int deg   = g_deg[v];

    const uint4* __restrict__ hbase = (const uint4*)g_hsh;
    const int*   __restrict__ cs    = g_csr + start;

    float acc[8];
    #pragma unroll
    for (int k = 0; k < 8; k++) acc[k] = 0.f;

    if (sub == 0) acc8(acc, hbase[(v << 3) + c]);   // self loop once

    // 4-way interleaved sub-lists (stride 4), unroll 4 -> MLP 4 per lane
    int i = sub;
    for (; i + 12 < deg; i += 16) {
        int s0 = __ldg(cs + i);
        int s1 = __ldg(cs + i + 4);
        int s2 = __ldg(cs + i + 8);
        int s3 = __ldg(cs + i + 12);
        uint4 v0 = hbase[(s0 << 3) + c];
        uint4 v1 = hbase[(s1 << 3) + c];
        uint4 v2 = hbase[(s2 << 3) + c];
        uint4 v3 = hbase[(s3 << 3) + c];
        acc8(acc, v0); acc8(acc, v1); acc8(acc, v2); acc8(acc, v3);
    }
    for (; i < deg; i += 4) {
        uint4 v0 = hbase[(__ldg(cs + i) << 3) + c];
        acc8(acc, v0);
    }

    #pragma unroll
    for (int k = 0; k < 8; k++) {
        acc[k] += __shfl_xor_sync(0xffffffffu, acc[k], 8);
        acc[k] += __shfl_xor_sync(0xffffffffu, acc[k], 16);
    }

    if (sub == 0) {
        const float* s3p = g_s3 + lsel * HID;
        const float* t3p = g_t3 + lsel * HID;
        float d = g_dinv[v];
        int j = c << 3;

        float o[8];
        #pragma unroll
        for (int k = 0; k < 8; k++)
            o[k] = fmaxf(fmaf(d * acc[k], s3p[j + k], t3p[j + k]), 0.f);

        if (rsel >= 0) {
            const float* r = (rsel == 0) ? g_x0 : g_x1;
            const float4 r0 = *(const float4*)(r + (v << 6) + j);
            const float4 r1 = *(const float4*)(r + (v << 6) + j + 4);
            o[0] += r0.x; o[1] += r0.y; o[2] += r0.z; o[3] += r0.w;
            o[4] += r1.x; o[5] += r1.y; o[6] += r1.z; o[7] += r1.w;
        }

        float* outp = (osel == 0) ? g_x0 : (osel == 1 ? g_x1 : dout);
        float4* op = (float4*)(outp + (v << 6) + j);
        op[0] = make_float4(o[0], o[1], o[2], o[3]);
        op[1] = make_float4(o[4], o[5], o[6], o[7]);
    }
}

// -------- launch --------
extern "C" void kernel_launch(void* const* d_in, const int* in_sizes, int n_in,
                              void* d_out, int out_size) {
    const float* x     = (const float*)d_in[0];
    const void*  ei    = d_in[1];
    const float* W1    = (const float*)d_in[2];
    const float* W2    = (const float*)d_in[3];
    const float* W3    = (const float*)d_in[4];
    const float* b     = (const float*)d_in[5];
    const float* gamma = (const float*)d_in[6];
    const float* beta  = (const float*)d_in[7];
    const float* mean  = (const float*)d_in[8];
    const float* var   = (const float*)d_in[9];
    float* out = (float*)d_out;

    const int T = 256;
    const int gN = (N_NODES + T - 1) / T;
    const int gE = (N_EDGES + T - 1) / T;
    const int gA = (N_NODES + 7) / 8;     // aggregate: 8 nodes/block (warp/node)

    // ---- preprocessing (reused by all 3 layers) ----
    init_all<<<gN, T>>>((const unsigned*)ei);
    deg_count<<<gE, T>>>(ei);
    scan1<<<N_SBLK, SCAN_B>>>();
    scan2_bn<<<1, 256>>>(b, gamma, beta, mean, var);
    scan3<<<gN, T>>>();
    csr_fill<<<gE, T>>>(ei);

    // layer 1: x(37) -> x0, no residual
    gemm_scale<IN_DIM><<<gN, T>>>(x, 0, W1);
    aggregate_ep<<<gA, T>>>(0, -1, 0, out);

    // layer 2: x0 -> x1, residual x0
    gemm_scale<HID><<<gN, T>>>(nullptr, 1, W2);
    aggregate_ep<<<gA, T>>>(1, 0, 1, out);

    // layer 3: x1 -> d_out, residual x1
    gemm_scale<HID><<<gN, T>>>(nullptr, 2, W3);
    aggregate_ep<<<gA, T>>>(2, 1, 2, out);
}

// round 12
// speedup vs baseline: 1.0368x; 1.0368x over previous
#include <cuda_runtime.h>
#include <cuda_fp16.h>

#define N_NODES 100000
#define N_EDGES 1000000
#define IN_DIM  37
#define HID     64
#define BN_EPS  1e-5f

#define NB_PRE   98          // preprocess blocks (<= SM count: co-resident)
#define T_PRE    1024

// -------- scratch (device globals; no allocation allowed) --------
__device__ __half g_hsh[N_NODES * HID];  // dinv-scaled GEMM output, fp16 (gather buffer)
__device__ float  g_x0 [N_NODES * HID];  // layer-1 output
__device__ float  g_x1 [N_NODES * HID];  // layer-2 output
__device__ int    g_deg   [N_NODES];     // real in-degree (no self loop)
__device__ float  g_dinv  [N_NODES];
__device__ int    g_bsum  [NB_PRE];
__device__ int    g_start [N_NODES];     // CSR row offsets (by col/target)
__device__ int    g_cursor[N_NODES];
__device__ int    g_csr   [N_EDGES];     // source node per CSR slot
__device__ float  g_s3[3 * HID];         // folded BN scale
__device__ float  g_t3[3 * HID];         // folded BN shift
__device__ int    g_cnt[3];              // global barrier counters (zeroed/call)
__device__ int    g_is64;

// -------- init: dtype detect + zero degree + zero barrier counters --------
__global__ void init_all(const unsigned* __restrict__ ei_raw) {
    int v = blockIdx.x * blockDim.x + threadIdx.x;
    if (v < N_NODES) g_deg[v] = 0;
    if (blockIdx.x == 0 && threadIdx.x < 3) g_cnt[threadIdx.x] = 0;
    if (blockIdx.x == 0 && threadIdx.x == 0) {
        int ok = 1;
        #pragma unroll 1
        for (int i = 0; i < 64; i++)
            if (ei_raw[2 * i + 1] != 0u) ok = 0;
        g_is64 = ok;  // all high words zero -> int64 layout
    }
}

// device-wide barrier: valid ONLY when all blocks are co-resident (NB_PRE <= #SM)
__device__ __forceinline__ void gbar(int* cnt) {
    __syncthreads();
    if (threadIdx.x == 0) {
        __threadfence();
        atomicAdd(cnt, 1);
        while (atomicAdd(cnt, 0) < NB_PRE) { }
    }
    __syncthreads();
    __threadfence();
}

// -------- fused preprocess: degree -> scan -> offsets/dinv/BN -> CSR fill ----
__global__ void __launch_bounds__(T_PRE, 1)
preprocess(const void* __restrict__ ei,
           const float* __restrict__ b,     const float* __restrict__ gamma,
           const float* __restrict__ beta,  const float* __restrict__ mean,
           const float* __restrict__ var) {
    __shared__ int s[T_PRE];
    __shared__ int boff_sh;

    const int t   = threadIdx.x;
    const int bid = blockIdx.x;
    const int g   = bid * T_PRE + t;
    const int STRIDE = NB_PRE * T_PRE;       // 100352
    const int is64 = g_is64;

    // ---- phase 1: degree count (vectorized edge loads) ----
    if (is64) {
        const longlong2* cols = (const longlong2*)((const long long*)ei + N_EDGES);
        for (int i = g; i < N_EDGES / 2; i += STRIDE) {
            longlong2 c = cols[i];
            atomicAdd(&g_deg[(int)c.x], 1);
            atomicAdd(&g_deg[(int)c.y], 1);
        }
    } else {
        const int4* cols = (const int4*)((const int*)ei + N_EDGES);
        for (int i = g; i < N_EDGES / 4; i += STRIDE) {
            int4 c = cols[i];
            atomicAdd(&g_deg[c.x], 1);
            atomicAdd(&g_deg[c.y], 1);
            atomicAdd(&g_deg[c.z], 1);
            atomicAdd(&g_deg[c.w], 1);
        }
    }
    gbar(&g_cnt[0]);

    // ---- phase 2: exclusive scan of degrees ----
    int dv = (g < N_NODES) ? g_deg[g] : 0;
    s[t] = dv;
    __syncthreads();
    #pragma unroll
    for (int off = 1; off < T_PRE; off <<= 1) {
        int x = (t >= off) ? s[t - off] : 0;
        __syncthreads();
        s[t] += x;
        __syncthreads();
    }
    int excl = s[t] - dv;
    if (t == T_PRE - 1) g_bsum[bid] = s[t];
    gbar(&g_cnt[1]);

    if (t == 0) {
        int sum = 0;
        #pragma unroll 1
        for (int j = 0; j < NB_PRE; j++) {
            if (j == bid) break;
            sum += g_bsum[j];
        }
        boff_sh = sum;
    }
    __syncthreads();

    if (g < N_NODES) {
        int st = excl + boff_sh;
        g_start[g]  = st;
        g_cursor[g] = st;
        g_dinv[g]   = rsqrtf((float)(dv + 1));   // +1 self loop
    }
    // folded BN (block 0 only)
    if (bid == 0 && t < 3 * HID) {
        float sc = gamma[t] * rsqrtf(var[t] + BN_EPS);
        g_s3[t] = sc;
        g_t3[t] = (b[t] - mean[t]) * sc + beta[t];
    }
    gbar(&g_cnt[2]);

    // ---- phase 3: CSR fill ----
    if (is64) {
        const long long* rows = (const long long*)ei;
        const long long* cols = rows + N_EDGES;
        for (int e = g; e < N_EDGES; e += STRIDE) {
            int row = (int)rows[e];
            int col = (int)cols[e];
            int pos = atomicAdd(&g_cursor[col], 1);
            g_csr[pos] = row;
        }
    } else {
        const int* rows = (const int*)ei;
        const int* cols = rows + N_EDGES;
        for (int e = g; e < N_EDGES; e += STRIDE) {
            int row = rows[e];
            int col = cols[e];
            int pos = atomicAdd(&g_cursor[col], 1);
            g_csr[pos] = row;
        }
    }
}

// -------- GEMM: hsh[v,:] = fp16( dinv[v] * (x[v,:] @ W) )  [R10 version] ----
// sel: 0 -> xext (harness input), 1 -> g_x0, 2 -> g_x1
template <int K>
__global__ void gemm_scale(const float* __restrict__ xext, int sel,
                           const float* __restrict__ W) {
    __shared__ __align__(16) float Wsh[K * HID];
    for (int i = threadIdx.x; i < K * HID; i += blockDim.x) Wsh[i] = W[i];
    __syncthreads();

    int v = blockIdx.x * blockDim.x + threadIdx.x;
    if (v >= N_NODES) return;

    const float* x = (sel == 0) ? xext : (sel == 1 ? g_x0 : g_x1);

    float4 acc[16];
    #pragma unroll
    for (int j = 0; j < 16; j++) acc[j] = make_float4(0.f, 0.f, 0.f, 0.f);

    const float* xr = x + v * K;
    #pragma unroll 4
    for (int k = 0; k < K; k++) {
        float xv = xr[k];
        const float4* wr = (const float4*)(Wsh + k * HID);
        #pragma unroll
        for (int j = 0; j < 16; j++) {
            float4 w = wr[j];
            acc[j].x += xv * w.x;
            acc[j].y += xv * w.y;
            acc[j].z += xv * w.z;
            acc[j].w += xv * w.w;
        }
    }

    float d = g_dinv[v];
    uint4* out = (uint4*)(g_hsh + (v << 6));
    #pragma unroll
    for (int j = 0; j < 8; j++) {
        float4 a0 = acc[2 * j];
        float4 a1 = acc[2 * j + 1];
        __half2 h0 = __floats2half2_rn(a0.x * d, a0.y * d);
        __half2 h1 = __floats2half2_rn(a0.z * d, a0.w * d);
        __half2 h2 = __floats2half2_rn(a1.x * d, a1.y * d);
        __half2 h3 = __floats2half2_rn(a1.z * d, a1.w * d);
        uint4 pk;
        pk.x = *(unsigned*)&h0;
        pk.y = *(unsigned*)&h1;
        pk.z = *(unsigned*)&h2;
        pk.w = *(unsigned*)&h3;
        out[j] = pk;
    }
}

// -------- fused aggregate + epilogue: warp-per-node  [R10 version] ----------
__device__ __forceinline__ void acc8(float* a, uint4 v) {
    const __half2* h = (const __half2*)&v;
    #pragma unroll
    for (int k = 0; k < 4; k++) {
        float2 f = __half22float2(h[k]);
        a[2 * k]     += f.x;
        a[2 * k + 1] += f.y;
    }
}

__global__ void aggregate_ep(int osel, int rsel, int lsel,
                             float* __restrict__ dout) {
    int lane = threadIdx.x & 31;
    int warp = threadIdx.x >> 5;
    int v = blockIdx.x * 8 + warp;         // 256 threads = 8 warps = 8 nodes
    if (v >= N_NODES) return;

    int c   = lane & 7;
    int sub = lane >> 3;

    int start = g_start[v];
    int deg   = g_deg[v];

    const uint4* __restrict__ hbase = (const uint4*)g_hsh;
    const int*   __restrict__ cs    = g_csr + start;

    float acc[8];
    #pragma unroll
    for (int k = 0; k < 8; k++) acc[k] = 0.f;

    // self loop handled once by sub-list 0
    if (sub == 0) acc8(acc, hbase[(v << 3) + c]);

    // 4-way interleaved edge sub-lists, unroll 2
    int i = sub;
    for (; i + 4 < deg; i += 8) {
        int s0 = __ldg(cs + i);
        int s1 = __ldg(cs + i + 4);
        uint4 v0 = hbase[(s0 << 3) + c];
        uint4 v1 = hbase[(s1 << 3) + c];
        acc8(acc, v0);
        acc8(acc, v1);
    }
    if (i < deg) {
        uint4 v0 = hbase[(__ldg(cs + i) << 3) + c];
        acc8(acc, v0);
    }

    // reduce over the 4 sub-lists (lanes c, c+8, c+16, c+24)
    #pragma unroll
    for (int k = 0; k < 8; k++) {
        acc[k] += __shfl_xor_sync(0xffffffffu, acc[k], 8);
        acc[k] += __shfl_xor_sync(0xffffffffu, acc[k], 16);
    }

    if (sub == 0) {
        const float* s3 = g_s3 + lsel * HID;
        const float* t3 = g_t3 + lsel * HID;
        float d = g_dinv[v];
        int j = c << 3;

        float o[8];
        #pragma unroll
        for (int k = 0; k < 8; k++)
            o[k] = fmaxf(fmaf(d * acc[k], s3[j + k], t3[j + k]), 0.f);

        if (rsel >= 0) {
            const float* r = (rsel == 0) ? g_x0 : g_x1;
            const float4 r0 = *(const float4*)(r + (v << 6) + j);
            const float4 r1 = *(const float4*)(r + (v << 6) + j + 4);
            o[0] += r0.x; o[1] += r0.y; o[2] += r0.z; o[3] += r0.w;
            o[4] += r1.x; o[5] += r1.y; o[6] += r1.z; o[7] += r1.w;
        }

        float* outp = (osel == 0) ? g_x0 : (osel == 1 ? g_x1 : dout);
        float4* op = (float4*)(outp + (v << 6) + j);
        op[0] = make_float4(o[0], o[1], o[2], o[3]);
        op[1] = make_float4(o[4], o[5], o[6], o[7]);
    }
}

// -------- launch --------
extern "C" void kernel_launch(void* const* d_in, const int* in_sizes, int n_in,
                              void* d_out, int out_size) {
    const float* x     = (const float*)d_in[0];
    const void*  ei    = d_in[1];
    const float* W1    = (const float*)d_in[2];
    const float* W2    = (const float*)d_in[3];
    const float* W3    = (const float*)d_in[4];
    const float* b     = (const float*)d_in[5];
    const float* gamma = (const float*)d_in[6];
    const float* beta  = (const float*)d_in[7];
    const float* mean  = (const float*)d_in[8];
    const float* var   = (const float*)d_in[9];
    float* out = (float*)d_out;

    const int T = 256;
    const int gN = (N_NODES + T - 1) / T;
    const int gA = (N_NODES + 7) / 8;     // aggregate: 8 nodes/block (warp/node)

    // ---- preprocessing (2 launches, reused by all 3 layers) ----
    init_all<<<gN, T>>>((const unsigned*)ei);
    preprocess<<<NB_PRE, T_PRE>>>(ei, b, gamma, beta, mean, var);

    // layer 1: x(37) -> x0, no residual
    gemm_scale<IN_DIM><<<gN, T>>>(x, 0, W1);
    aggregate_ep<<<gA, T>>>(0, -1, 0, out);

    // layer 2: x0 -> x1, residual x0
    gemm_scale<HID><<<gN, T>>>(nullptr, 1, W2);
    aggregate_ep<<<gA, T>>>(1, 0, 1, out);

    // layer 3: x1 -> d_out, residual x1
    gemm_scale<HID><<<gN, T>>>(nullptr, 2, W3);
    aggregate_ep<<<gA, T>>>(2, 1, 2, out);
}